// round 2
// baseline (speedup 1.0000x reference)
#include <cuda_runtime.h>
#include <stdint.h>

// Problem constants (fixed by the reference setup_inputs()).
#define N_ROWS 262144
#define M_ROWS 1048576
#define DCOLS  128
#define VEC    (DCOLS / 4)   // 32 float4 per row -> one warp covers a full row

// Scratch (static __device__ allocations are allowed).
__device__ int g_mode;                 // 0: A as i64, 1: A as i32, 2: B as i64, 3: B as i32
__device__ int g_idx32[M_ROWS];       // normalized int32 copy of sorted_index
__device__ int g_offsets[N_ROWS + 1]; // segment offsets

// ---------------------------------------------------------------------------
// Kernel 0: dtype/slot detection. One warp. For each candidate interpretation,
// 32 strided samples must be in [0, N_ROWS) and monotone non-decreasing.
// pos (arange to M-1 >= N) fails range; wrong-dtype reads fail range or
// monotonicity. First candidate that passes wins.
// ---------------------------------------------------------------------------
__global__ void detect_kernel(const void* A, const void* B) {
    const int lane = threadIdx.x;
    const unsigned FULL = 0xFFFFFFFFu;
    long long i = (long long)lane * (M_ROWS - 1) / 31;

    const void* ptrs[2] = {A, B};
    #pragma unroll
    for (int mode = 0; mode < 4; mode++) {
        const void* p = ptrs[mode >> 1];
        long long v;
        if (mode & 1) v = (long long)((const int*)p)[i];
        else          v = ((const long long*)p)[i];
        bool ok = (v >= 0) && (v < N_ROWS);
        long long prev = __shfl_up_sync(FULL, v, 1);
        if (lane > 0) ok = ok && (v >= prev);
        if (__all_sync(FULL, ok)) {
            if (lane == 0) g_mode = mode;
            return;
        }
    }
    if (lane == 0) g_mode = 0;  // fallback: assume A as int64
}

// ---------------------------------------------------------------------------
// Kernel 0b: normalize the detected index buffer into int32 scratch.
// ---------------------------------------------------------------------------
__global__ void convert_kernel(const void* A, const void* B) {
    int i = blockIdx.x * blockDim.x + threadIdx.x;
    if (i >= M_ROWS) return;
    int mode = g_mode;
    const void* p = (mode < 2) ? A : B;
    int v;
    if (mode & 1) v = ((const int*)p)[i];
    else          v = (int)((const long long*)p)[i];
    g_idx32[i] = v;
}

// ---------------------------------------------------------------------------
// Kernel 1: per-output-row lower_bound over the sorted int32 index.
// offsets[n] = first i with idx[i] >= n; segment for row n = [off[n], off[n+1]).
// ---------------------------------------------------------------------------
__global__ void build_offsets_kernel() {
    int n = blockIdx.x * blockDim.x + threadIdx.x;
    if (n > N_ROWS) return;
    int lo = 0, hi = M_ROWS;
    #pragma unroll 1
    while (lo < hi) {
        int mid = (lo + hi) >> 1;
        if (g_idx32[mid] < n) lo = mid + 1;
        else                  hi = mid;
    }
    g_offsets[n] = lo;
}

// ---------------------------------------------------------------------------
// Kernel 2: segmented sum. One warp per output row; lane l owns one float4
// (32 lanes x 16B = 512B = the whole D=128 row). acc = self[n] + run of
// contiguous value rows; single coalesced store. Zero atomics; every value
// row read exactly once -> minimal HBM traffic.
// ---------------------------------------------------------------------------
__global__ void segment_sum_kernel(const float4* __restrict__ self_t,
                                   const float4* __restrict__ value,
                                   float4* __restrict__ out) {
    int gwarp = (int)((blockIdx.x * blockDim.x + threadIdx.x) >> 5);
    int lane  = threadIdx.x & 31;
    if (gwarp >= N_ROWS) return;

    int beg = g_offsets[gwarp];
    int end = g_offsets[gwarp + 1];

    long long rowbase = (long long)gwarp * VEC + lane;
    float4 acc = self_t[rowbase];

    // Dual accumulators for MLP on longer runs; runs avg ~4 rows.
    float4 acc2 = make_float4(0.f, 0.f, 0.f, 0.f);
    int i = beg;
    for (; i + 1 < end; i += 2) {
        float4 v0 = value[(long long)i * VEC + lane];
        float4 v1 = value[(long long)(i + 1) * VEC + lane];
        acc.x  += v0.x; acc.y  += v0.y; acc.z  += v0.z; acc.w  += v0.w;
        acc2.x += v1.x; acc2.y += v1.y; acc2.z += v1.z; acc2.w += v1.w;
    }
    if (i < end) {
        float4 v = value[(long long)i * VEC + lane];
        acc.x += v.x; acc.y += v.y; acc.z += v.z; acc.w += v.w;
    }
    acc.x += acc2.x; acc.y += acc2.y; acc.z += acc2.z; acc.w += acc2.w;

    out[rowbase] = acc;
}

// ---------------------------------------------------------------------------
// Launch. Inputs identified by element count (robust to slot order):
//   self_tensor : N*D = 33554432 elements
//   value       : M*D = 134217728 elements
//   index/pos   : everything else (dtype detected on device)
// ---------------------------------------------------------------------------
extern "C" void kernel_launch(void* const* d_in, const int* in_sizes, int n_in,
                              void* d_out, int out_size) {
    const float4* self_t = nullptr;
    const float4* value  = nullptr;
    const void*   cand[2] = {nullptr, nullptr};
    int nc = 0;
    for (int i = 0; i < n_in; i++) {
        if (in_sizes[i] == N_ROWS * DCOLS && !self_t) {
            self_t = (const float4*)d_in[i];
        } else if (in_sizes[i] == M_ROWS * DCOLS && !value) {
            value = (const float4*)d_in[i];
        } else if (nc < 2) {
            cand[nc++] = d_in[i];
        }
    }
    // Fallbacks to the documented order if size matching failed.
    if (!self_t)  self_t  = (const float4*)d_in[0];
    if (!value)   value   = (const float4*)d_in[1];
    if (!cand[0]) cand[0] = (n_in > 2) ? d_in[2] : d_in[0];
    if (!cand[1]) cand[1] = (n_in > 3) ? d_in[3] : cand[0];

    float4* out = (float4*)d_out;

    detect_kernel<<<1, 32>>>(cand[0], cand[1]);
    convert_kernel<<<(M_ROWS + 255) / 256, 256>>>(cand[0], cand[1]);
    build_offsets_kernel<<<(N_ROWS + 1 + 255) / 256, 256>>>();

    // One warp per output row; 8 warps per CTA.
    segment_sum_kernel<<<N_ROWS / 8, 256>>>(self_t, value, out);
}

// round 3
// speedup vs baseline: 1.0158x; 1.0158x over previous
#include <cuda_runtime.h>
#include <stdint.h>

// Problem constants (fixed by the reference setup_inputs()).
#define N_ROWS 262144
#define M_ROWS 1048576
#define DCOLS  128
#define VEC    (DCOLS / 4)   // 32 float4 per row -> one warp covers a full row

// Scratch (static __device__ allocations are allowed).
__device__ int g_mode;                 // 0: A as i64, 1: A as i32, 2: B as i64, 3: B as i32
__device__ int g_offsets[N_ROWS + 1];  // segment offsets

// ---------------------------------------------------------------------------
// Mode-dispatched index load.
// ---------------------------------------------------------------------------
__device__ __forceinline__ int load_idx(const void* A, const void* B, int mode, int i) {
    const void* p = (mode < 2) ? A : B;
    if (mode & 1) return ((const int*)p)[i];
    return (int)((const long long*)p)[i];
}

// ---------------------------------------------------------------------------
// Kernel 0: dtype/slot detection. One warp. For each candidate interpretation,
// 32 strided samples must be in [0, N_ROWS) and monotone non-decreasing.
// pos (arange up to M-1 >= N) fails range; wrong-dtype reads fail range or
// monotonicity. First candidate that passes wins.
// ---------------------------------------------------------------------------
__global__ void detect_kernel(const void* A, const void* B) {
    const int lane = threadIdx.x;
    const unsigned FULL = 0xFFFFFFFFu;
    long long i = (long long)lane * (M_ROWS - 1) / 31;

    const void* ptrs[2] = {A, B};
    #pragma unroll
    for (int mode = 0; mode < 4; mode++) {
        const void* p = ptrs[mode >> 1];
        long long v;
        if (mode & 1) v = (long long)((const int*)p)[i];
        else          v = ((const long long*)p)[i];
        bool ok = (v >= 0) && (v < N_ROWS);
        long long prev = __shfl_up_sync(FULL, v, 1);
        if (lane > 0) ok = ok && (v >= prev);
        if (__all_sync(FULL, ok)) {
            if (lane == 0) g_mode = mode;
            return;
        }
    }
    if (lane == 0) g_mode = 0;  // fallback: assume A as int64
}

// ---------------------------------------------------------------------------
// Kernel 1: difference-scatter offsets. Thread i reads idx[i-1], idx[i]
// (linear, coalesced) and fills offsets[n] = i for n in (idx[i-1], idx[i]].
// Thread M-1 also fills the trailing rows with M. Total stores = N+1.
// offsets[n] = first value-row with index >= n.
// ---------------------------------------------------------------------------
__global__ void build_offsets_kernel(const void* A, const void* B) {
    int i = blockIdx.x * blockDim.x + threadIdx.x;
    if (i >= M_ROWS) return;
    int mode = g_mode;
    int cur  = load_idx(A, B, mode, i);
    int prev = (i == 0) ? -1 : load_idx(A, B, mode, i - 1);
    for (int n = prev + 1; n <= cur; n++) g_offsets[n] = i;
    if (i == M_ROWS - 1) {
        for (int n = cur + 1; n <= N_ROWS; n++) g_offsets[n] = M_ROWS;
    }
}

// ---------------------------------------------------------------------------
// Kernel 2: segmented sum. One warp per output row; lane l owns one float4
// (32 lanes x 16B = 512B = the whole D=128 row). acc = self[n] + contiguous
// run of value rows; single coalesced store. Zero atomics; every value row
// read exactly once. Streaming hints (.cs) keep the one-touch streams from
// thrashing L2; 4-deep unroll for MLP.
// ---------------------------------------------------------------------------
__global__ void segment_sum_kernel(const float4* __restrict__ self_t,
                                   const float4* __restrict__ value,
                                   float4* __restrict__ out) {
    int gwarp = (int)((blockIdx.x * blockDim.x + threadIdx.x) >> 5);
    int lane  = threadIdx.x & 31;
    if (gwarp >= N_ROWS) return;

    int beg = g_offsets[gwarp];
    int end = g_offsets[gwarp + 1];

    long long rowbase = (long long)gwarp * VEC + lane;
    float4 acc0 = __ldcs(&self_t[rowbase]);
    float4 acc1 = make_float4(0.f, 0.f, 0.f, 0.f);
    float4 acc2 = make_float4(0.f, 0.f, 0.f, 0.f);
    float4 acc3 = make_float4(0.f, 0.f, 0.f, 0.f);

    const float4* vp = value + (long long)beg * VEC + lane;
    int len = end - beg;

    int i = 0;
    for (; i + 3 < len; i += 4) {
        float4 v0 = __ldcs(vp + (long long)(i    ) * VEC);
        float4 v1 = __ldcs(vp + (long long)(i + 1) * VEC);
        float4 v2 = __ldcs(vp + (long long)(i + 2) * VEC);
        float4 v3 = __ldcs(vp + (long long)(i + 3) * VEC);
        acc0.x += v0.x; acc0.y += v0.y; acc0.z += v0.z; acc0.w += v0.w;
        acc1.x += v1.x; acc1.y += v1.y; acc1.z += v1.z; acc1.w += v1.w;
        acc2.x += v2.x; acc2.y += v2.y; acc2.z += v2.z; acc2.w += v2.w;
        acc3.x += v3.x; acc3.y += v3.y; acc3.z += v3.z; acc3.w += v3.w;
    }
    for (; i < len; i++) {
        float4 v = __ldcs(vp + (long long)i * VEC);
        acc0.x += v.x; acc0.y += v.y; acc0.z += v.z; acc0.w += v.w;
    }

    acc0.x += acc1.x + acc2.x + acc3.x;
    acc0.y += acc1.y + acc2.y + acc3.y;
    acc0.z += acc1.z + acc2.z + acc3.z;
    acc0.w += acc1.w + acc2.w + acc3.w;

    __stcs(&out[rowbase], acc0);
}

// ---------------------------------------------------------------------------
// Launch. Inputs identified by element count (robust to slot order):
//   self_tensor : N*D = 33554432 elements
//   value       : M*D = 134217728 elements
//   index/pos   : everything else (dtype detected on device)
// ---------------------------------------------------------------------------
extern "C" void kernel_launch(void* const* d_in, const int* in_sizes, int n_in,
                              void* d_out, int out_size) {
    const float4* self_t = nullptr;
    const float4* value  = nullptr;
    const void*   cand[2] = {nullptr, nullptr};
    int nc = 0;
    for (int i = 0; i < n_in; i++) {
        if (in_sizes[i] == N_ROWS * DCOLS && !self_t) {
            self_t = (const float4*)d_in[i];
        } else if (in_sizes[i] == M_ROWS * DCOLS && !value) {
            value = (const float4*)d_in[i];
        } else if (nc < 2) {
            cand[nc++] = d_in[i];
        }
    }
    if (!self_t)  self_t  = (const float4*)d_in[0];
    if (!value)   value   = (const float4*)d_in[1];
    if (!cand[0]) cand[0] = (n_in > 2) ? d_in[2] : d_in[0];
    if (!cand[1]) cand[1] = (n_in > 3) ? d_in[3] : cand[0];

    float4* out = (float4*)d_out;

    detect_kernel<<<1, 32>>>(cand[0], cand[1]);
    build_offsets_kernel<<<(M_ROWS + 255) / 256, 256>>>(cand[0], cand[1]);

    // One warp per output row; 8 warps per CTA.
    segment_sum_kernel<<<N_ROWS / 8, 256>>>(self_t, value, out);
}

// round 4
// speedup vs baseline: 1.1604x; 1.1423x over previous
#include <cuda_runtime.h>
#include <stdint.h>

// Problem constants (fixed by the reference setup_inputs()).
#define N_ROWS 262144
#define M_ROWS 1048576
#define DCOLS  128
#define VEC    (DCOLS / 4)   // 32 float4 per row -> one warp covers a full row

// Scratch (static __device__ allocations are allowed).
__device__ int g_offsets[N_ROWS + 1];  // segment offsets

// ---------------------------------------------------------------------------
// Warp-collective dtype/slot detection (executed redundantly by warp 0 of
// every build_offsets CTA). 32 strided samples must be in [0, N_ROWS) and
// monotone non-decreasing. pos (arange to M-1 >= N_ROWS) fails range;
// wrong-dtype reads fail range or monotonicity.
// Returns mode: 0=A as i64, 1=A as i32, 2=B as i64, 3=B as i32.
// ---------------------------------------------------------------------------
__device__ __forceinline__ int detect_mode(const void* A, const void* B, int lane) {
    const unsigned FULL = 0xFFFFFFFFu;
    long long i = (long long)lane * (M_ROWS - 1) / 31;
    const void* ptrs[2] = {A, B};
    #pragma unroll
    for (int mode = 0; mode < 4; mode++) {
        const void* p = ptrs[mode >> 1];
        long long v;
        if (mode & 1) v = (long long)((const int*)p)[i];
        else          v = ((const long long*)p)[i];
        bool ok = (v >= 0) && (v < N_ROWS);
        long long prev = __shfl_up_sync(FULL, v, 1);
        if (lane > 0) ok = ok && (v >= prev);
        if (__all_sync(FULL, ok)) return mode;   // uniform across warp
    }
    return 0;  // fallback
}

__device__ __forceinline__ int load_idx(const void* A, const void* B, int mode, int i) {
    const void* p = (mode < 2) ? A : B;
    if (mode & 1) return ((const int*)p)[i];
    return (int)((const long long*)p)[i];
}

// ---------------------------------------------------------------------------
// Kernel 1: detection (in-block) + difference-scatter offsets.
// Thread i reads idx[i-1], idx[i] (linear, coalesced) and fills
// offsets[n] = i for n in (idx[i-1], idx[i]]. Thread M-1 fills trailing rows.
// offsets[n] = first value-row with index >= n.
// ---------------------------------------------------------------------------
__global__ void build_offsets_kernel(const void* A, const void* B) {
    __shared__ int s_mode;
    if (threadIdx.x < 32) {
        int m = detect_mode(A, B, threadIdx.x);
        if (threadIdx.x == 0) s_mode = m;
    }
    __syncthreads();
    int mode = s_mode;

    int i = blockIdx.x * blockDim.x + threadIdx.x;
    if (i >= M_ROWS) return;
    int cur  = load_idx(A, B, mode, i);
    int prev = (i == 0) ? -1 : load_idx(A, B, mode, i - 1);
    for (int n = prev + 1; n <= cur; n++) g_offsets[n] = i;
    if (i == M_ROWS - 1) {
        for (int n = cur + 1; n <= N_ROWS; n++) g_offsets[n] = M_ROWS;
    }
}

// ---------------------------------------------------------------------------
// Kernel 2: segmented sum, TWO consecutive output rows per warp.
// Lane l owns one float4 column (32 lanes x 16B = 512B = whole D=128 row).
// The two segments are adjacent in value and are independent accumulation
// chains, so the main loop interleaves their loads for 2x MLP — this is the
// win for short (len<4) segments, which are ~43% of rows at Poisson(4).
// Zero atomics; every value row read exactly once; streaming (.cs) hints.
// ---------------------------------------------------------------------------
__global__ void segment_sum_kernel(const float4* __restrict__ self_t,
                                   const float4* __restrict__ value,
                                   float4* __restrict__ out) {
    int gw   = (int)((blockIdx.x * blockDim.x + threadIdx.x) >> 5);
    int lane = threadIdx.x & 31;
    if (gw >= N_ROWS / 2) return;

    int r0   = gw * 2;
    int beg0 = g_offsets[r0];
    int mid  = g_offsets[r0 + 1];
    int end1 = g_offsets[r0 + 2];

    long long rb0 = (long long)r0 * VEC + lane;
    float4 a0 = __ldcs(&self_t[rb0]);
    float4 a1 = __ldcs(&self_t[rb0 + VEC]);

    const float4* p0 = value + (long long)beg0 * VEC + lane;
    const float4* p1 = value + (long long)mid  * VEC + lane;
    int l0 = mid - beg0;
    int l1 = end1 - mid;
    int c  = (l0 < l1) ? l0 : l1;

    // Interleaved phase: both rows advance together (independent chains).
    int i = 0;
    for (; i < c; i++) {
        float4 v0 = __ldcs(p0 + (long long)i * VEC);
        float4 v1 = __ldcs(p1 + (long long)i * VEC);
        a0.x += v0.x; a0.y += v0.y; a0.z += v0.z; a0.w += v0.w;
        a1.x += v1.x; a1.y += v1.y; a1.z += v1.z; a1.w += v1.w;
    }

    // Drain row 0 remainder with a second accumulator (2-wide MLP).
    if (i < l0) {
        float4 e = make_float4(0.f, 0.f, 0.f, 0.f);
        int j = i;
        for (; j + 1 < l0; j += 2) {
            float4 v0 = __ldcs(p0 + (long long)j * VEC);
            float4 v1 = __ldcs(p0 + (long long)(j + 1) * VEC);
            a0.x += v0.x; a0.y += v0.y; a0.z += v0.z; a0.w += v0.w;
            e.x  += v1.x; e.y  += v1.y; e.z  += v1.z; e.w  += v1.w;
        }
        if (j < l0) {
            float4 v = __ldcs(p0 + (long long)j * VEC);
            a0.x += v.x; a0.y += v.y; a0.z += v.z; a0.w += v.w;
        }
        a0.x += e.x; a0.y += e.y; a0.z += e.z; a0.w += e.w;
    }

    // Drain row 1 remainder.
    if (i < l1) {
        float4 e = make_float4(0.f, 0.f, 0.f, 0.f);
        int j = i;
        for (; j + 1 < l1; j += 2) {
            float4 v0 = __ldcs(p1 + (long long)j * VEC);
            float4 v1 = __ldcs(p1 + (long long)(j + 1) * VEC);
            a1.x += v0.x; a1.y += v0.y; a1.z += v0.z; a1.w += v0.w;
            e.x  += v1.x; e.y  += v1.y; e.z  += v1.z; e.w  += v1.w;
        }
        if (j < l1) {
            float4 v = __ldcs(p1 + (long long)j * VEC);
            a1.x += v.x; a1.y += v.y; a1.z += v.z; a1.w += v.w;
        }
        a1.x += e.x; a1.y += e.y; a1.z += e.z; a1.w += e.w;
    }

    __stcs(&out[rb0], a0);
    __stcs(&out[rb0 + VEC], a1);
}

// ---------------------------------------------------------------------------
// Launch. Inputs identified by element count (robust to slot order):
//   self_tensor : N*D = 33554432 elements
//   value       : M*D = 134217728 elements
//   index/pos   : everything else (dtype detected on device)
// ---------------------------------------------------------------------------
extern "C" void kernel_launch(void* const* d_in, const int* in_sizes, int n_in,
                              void* d_out, int out_size) {
    const float4* self_t = nullptr;
    const float4* value  = nullptr;
    const void*   cand[2] = {nullptr, nullptr};
    int nc = 0;
    for (int i = 0; i < n_in; i++) {
        if (in_sizes[i] == N_ROWS * DCOLS && !self_t) {
            self_t = (const float4*)d_in[i];
        } else if (in_sizes[i] == M_ROWS * DCOLS && !value) {
            value = (const float4*)d_in[i];
        } else if (nc < 2) {
            cand[nc++] = d_in[i];
        }
    }
    if (!self_t)  self_t  = (const float4*)d_in[0];
    if (!value)   value   = (const float4*)d_in[1];
    if (!cand[0]) cand[0] = (n_in > 2) ? d_in[2] : d_in[0];
    if (!cand[1]) cand[1] = (n_in > 3) ? d_in[3] : cand[0];

    float4* out = (float4*)d_out;

    build_offsets_kernel<<<(M_ROWS + 255) / 256, 256>>>(cand[0], cand[1]);

    // One warp per two output rows; 8 warps per CTA.
    segment_sum_kernel<<<(N_ROWS / 2) / 8, 256>>>(self_t, value, out);
}